// round 1
// baseline (speedup 1.0000x reference)
#include <cuda_runtime.h>
#include <math.h>

// Problem constants
#define BATCH 32
#define C     256     // Cin
#define COUT  256
#define H     56
#define W     56

// Tiling
#define CI_T  8       // Cin chunk per stage
#define TH    4       // output rows per block
#define TC    64      // couts per block
#define SIN_STRIDE 72 // padded smem column stride (conflict-free: 4 rows x 8 cols -> 32 banks)

// Block: 256 threads = 8 cout-groups (tx_c) x 32 spatial (tx_s)
// tx_s -> oh_l = tx_s>>3 (0..3), basec = tx_s&7 ; thread's 7 outputs at ow = basec + 8*p
// Each thread accumulates 8 couts x 7 ow = 56 outputs.

__device__ __forceinline__ float quant_fixed(float x) {
    // round_to_fixed: floor(x / 2^-16) * 2^-16, clip to [-2^15, 2^15 - 1]
    float v = floorf(x * 65536.0f) * (1.0f / 65536.0f);
    return fminf(fmaxf(v, -32768.0f), 32767.0f);
}

__global__ __launch_bounds__(256, 2)
void conv_shift_kernel(const float* __restrict__ in,
                       const float* __restrict__ shiftp,
                       const float* __restrict__ signp,
                       const float* __restrict__ biasp,
                       float* __restrict__ out)
{
    __shared__ float s_in[CI_T][6][SIN_STRIDE];
    __shared__ float s_w[CI_T][TC][9];

    const int tid   = threadIdx.x;
    const int oh0   = blockIdx.x * TH;
    const int cout0 = blockIdx.y * TC;
    const int b     = blockIdx.z;

    const int tx_c  = tid >> 5;    // 0..7 (warp id)
    const int tx_s  = tid & 31;
    const int oh_l  = tx_s >> 3;   // 0..3
    const int basec = tx_s & 7;    // 0..7

    float acc[8][7];
    #pragma unroll
    for (int j = 0; j < 8; ++j)
        #pragma unroll
        for (int p = 0; p < 7; ++p) acc[j][p] = 0.0f;

    const float* in_b = in + (size_t)b * C * H * W;

    for (int ci0 = 0; ci0 < C; ci0 += CI_T) {
        // ---- stage input tile (with halo), quantize inline ----
        #pragma unroll 1
        for (int idx = tid; idx < CI_T * 6 * 58; idx += 256) {
            int cc  = idx / (6 * 58);
            int rem = idx - cc * (6 * 58);
            int r   = rem / 58;
            int col = rem - r * 58;
            int ih  = oh0 + r - 1;
            int iw  = col - 1;
            float v = 0.0f;
            if (ih >= 0 && ih < H && iw >= 0 && iw < W) {
                float x = in_b[(size_t)(ci0 + cc) * (H * W) + ih * W + iw];
                v = quant_fixed(x);
            }
            s_in[cc][r][col] = v;
        }
        // ---- stage weights, quantize inline: w = sign(round(sign)) * 2^round(clamp(shift)) ----
        #pragma unroll 1
        for (int idx = tid; idx < CI_T * TC * 9; idx += 256) {
            int cc  = idx / (TC * 9);
            int rem = idx - cc * (TC * 9);
            int c   = rem / 9;
            int q   = rem - c * 9;
            size_t g = ((size_t)(cout0 + c) * C + (ci0 + cc)) * 9 + q;
            float sr = rintf(fminf(fmaxf(shiftp[g], -14.0f), 0.0f));
            float gr = rintf(signp[g]);
            float sg = (gr > 0.0f) ? 1.0f : (gr < 0.0f ? -1.0f : 0.0f);
            s_w[cc][c][q] = ldexpf(sg, (int)sr);   // exact power-of-two weight
        }
        __syncthreads();

        // ---- compute: 8 ci x 3 kh x 3 kw x (8 cout x 7 ow) FMAs ----
        #pragma unroll 1
        for (int cc = 0; cc < CI_T; ++cc) {
            #pragma unroll
            for (int kh = 0; kh < 3; ++kh) {
                float xv[21];
                #pragma unroll
                for (int p = 0; p < 7; ++p)
                    #pragma unroll
                    for (int kw = 0; kw < 3; ++kw)
                        xv[p * 3 + kw] = s_in[cc][oh_l + kh][basec + 8 * p + kw];
                #pragma unroll
                for (int kw = 0; kw < 3; ++kw) {
                    float wv[8];
                    #pragma unroll
                    for (int j = 0; j < 8; ++j)
                        wv[j] = s_w[cc][tx_c * 8 + j][kh * 3 + kw];
                    #pragma unroll
                    for (int j = 0; j < 8; ++j)
                        #pragma unroll
                        for (int p = 0; p < 7; ++p)
                            acc[j][p] = fmaf(wv[j], xv[p * 3 + kw], acc[j][p]);
                }
            }
        }
        __syncthreads();
    }

    // ---- epilogue: bias (fixed-point quantized) + coalesced stores ----
    #pragma unroll
    for (int j = 0; j < 8; ++j) {
        int cout = cout0 + tx_c * 8 + j;
        float bq = quant_fixed(biasp[cout]);
        size_t ob = ((size_t)b * COUT + cout) * (H * W) + (size_t)(oh0 + oh_l) * W;
        #pragma unroll
        for (int p = 0; p < 7; ++p)
            out[ob + basec + 8 * p] = acc[j][p] + bq;
    }
}

extern "C" void kernel_launch(void* const* d_in, const int* in_sizes, int n_in,
                              void* d_out, int out_size)
{
    const float* in    = (const float*)d_in[0];
    const float* shift = (const float*)d_in[1];
    const float* sign  = (const float*)d_in[2];
    const float* bias  = (const float*)d_in[3];
    float* out = (float*)d_out;

    dim3 grid(H / TH, COUT / TC, BATCH);   // 14 x 4 x 32
    conv_shift_kernel<<<grid, 256>>>(in, shift, sign, bias, out);
}

// round 2
// speedup vs baseline: 5.3691x; 5.3691x over previous
#include <cuda_runtime.h>
#include <cuda_bf16.h>
#include <math.h>

#define BATCH 32
#define C     256
#define COUT  256
#define H     56
#define W     56

// Packed quantized weights: [ci_chunk(32)][tap(9)][cout(256)][pos(8)]
// pos permutation puts (ci, ci+4) adjacent for LDS.64 B-fragment loads.
__device__ unsigned int g_wq[32u * 9u * 256u * 8u];

__device__ __forceinline__ float quant_fixed(float x) {
    float v = floorf(x * 65536.0f) * (1.0f / 65536.0f);
    return fminf(fmaxf(v, -32768.0f), 32767.0f);
}

// ---------------- weight pre-quantization kernel ----------------
__global__ void quant_weights_kernel(const float* __restrict__ shiftp,
                                     const float* __restrict__ signp)
{
    int gid = blockIdx.x * blockDim.x + threadIdx.x;   // linear over [cout][ci][tap]
    int cout = gid / (C * 9);
    int rem  = gid - cout * (C * 9);
    int ci   = rem / 9;
    int tap  = rem - ci * 9;

    float sr = rintf(fminf(fmaxf(shiftp[gid], -14.0f), 0.0f));
    float g  = rintf(signp[gid]);
    float sg = (g > 0.0f) ? 1.0f : ((g < 0.0f) ? -1.0f : 0.0f);
    float wf = ldexpf(sg, (int)sr);                    // exact power-of-two (or 0)
    unsigned short u = __bfloat16_as_ushort(__float2bfloat16(wf)); // exact in bf16
    unsigned int packed = ((unsigned int)u << 16) | u; // duplicated for (hi,lo) K-pair

    int ci_l = ci & 7;
    int pos  = ((ci_l & 3) << 1) | (ci_l >> 2);        // (c, c+4) adjacent
    g_wq[(((ci >> 3) * 9 + tap) * 256 + cout) * 8 + pos] = packed;
}

// ---------------- main MMA conv ----------------
// CTA: M=112 (2 output rows), N=128 couts. 8 warps = 2(M-split: 4/3 mtiles) x 4(N-split: 32 couts).
// K-step (16) = 8 ci x {hi,lo}. 32 ci-chunks x 9 taps.

template<int MTS>
__device__ __forceinline__ void conv_body(
    const float* __restrict__ in_b,
    const float* __restrict__ biasp,
    float* __restrict__ out_b,
    unsigned int* s_x, unsigned int* s_w,
    int oh_base, int cout0, int tid, int wn, int mt0)
{
    const int lane = tid & 31;
    const int qc = lane & 3;     // k-quad  (ci slot)
    const int qr = lane >> 2;    // m/n row within fragment

    // Spatial word-offsets into s_x plane (ohl*58 + ow) for rows m and m+8 of each m-tile
    int offA[MTS], offB[MTS];
#pragma unroll
    for (int mt = 0; mt < MTS; ++mt) {
        int mA = (mt0 + mt) * 16 + qr;
        int mB = mA + 8;
        offA[mt] = (mA / 56) * 58 + (mA % 56);
        offB[mt] = (mB / 56) * 58 + (mB % 56);
    }

    float acc[MTS][4][4];
#pragma unroll
    for (int mt = 0; mt < MTS; ++mt)
#pragma unroll
        for (int nn = 0; nn < 4; ++nn)
#pragma unroll
            for (int r = 0; r < 4; ++r) acc[mt][nn][r] = 0.0f;

    const int qc232 = qc * 232;

    for (int chunk = 0; chunk < 32; ++chunk) {
        // ---- stage x: 8 ci x 4 rows x 58 cols, quantize + hi/lo bf16 split, packed u32 ----
        const float* inc = in_b + (size_t)chunk * 8 * H * W;
#pragma unroll
        for (int it = 0; it < 8; ++it) {
            int idx = tid + it * 256;
            if (idx < 1856) {
                int ci_l = idx / 232;
                int rem  = idx - ci_l * 232;
                int row  = rem / 58;
                int col  = rem - row * 58;
                int ih = oh_base + row - 1;
                int iw = col - 1;
                float v = 0.0f;
                if (ih >= 0 && ih < H && iw >= 0 && iw < W)
                    v = quant_fixed(inc[ci_l * (H * W) + ih * W + iw]);
                __nv_bfloat16 hi = __float2bfloat16(v);
                float hif = __bfloat162float(hi);
                __nv_bfloat16 lo = __float2bfloat16(v - hif);
                s_x[idx] = ((unsigned int)__bfloat16_as_ushort(lo) << 16)
                          | (unsigned int)__bfloat16_as_ushort(hi);
            }
        }
        // ---- stage w: straight float4 copy, layout matches smem [tap][cout_local][pos] ----
#pragma unroll
        for (int it = 0; it < 9; ++it) {
            const float4* src = (const float4*)(g_wq + (size_t)(chunk * 9 + it) * 2048 + cout0 * 8);
            ((float4*)s_w)[it * 256 + tid] = src[tid];
        }
        __syncthreads();

#pragma unroll
        for (int tap = 0; tap < 9; ++tap) {
            const int kh = tap / 3, kw = tap - kh * 3;
            const int tadd = kh * 58 + kw;

            // B fragments: 4 n8 tiles; LDS.64 grabs w(ci=qc) and w(ci=qc+4)
            unsigned int b0[4], b1[4];
#pragma unroll
            for (int nn = 0; nn < 4; ++nn) {
                int cl = wn * 32 + nn * 8 + qr;
                uint2 bb = *(const uint2*)&s_w[tap * 1024 + cl * 8 + 2 * qc];
                b0[nn] = bb.x; b1[nn] = bb.y;
            }
#pragma unroll
            for (int mt = 0; mt < MTS; ++mt) {
                unsigned int a0 = s_x[qc232 + tadd + offA[mt]];
                unsigned int a1 = s_x[qc232 + tadd + offB[mt]];
                unsigned int a2 = s_x[qc232 + 928 + tadd + offA[mt]];
                unsigned int a3 = s_x[qc232 + 928 + tadd + offB[mt]];
#pragma unroll
                for (int nn = 0; nn < 4; ++nn) {
                    asm volatile(
                        "mma.sync.aligned.m16n8k16.row.col.f32.bf16.bf16.f32 "
                        "{%0,%1,%2,%3}, {%4,%5,%6,%7}, {%8,%9}, {%0,%1,%2,%3};\n"
                        : "+f"(acc[mt][nn][0]), "+f"(acc[mt][nn][1]),
                          "+f"(acc[mt][nn][2]), "+f"(acc[mt][nn][3])
                        : "r"(a0), "r"(a1), "r"(a2), "r"(a3),
                          "r"(b0[nn]), "r"(b1[nn]));
                }
            }
        }
        __syncthreads();
    }

    // ---- epilogue: bias + stores ----
#pragma unroll
    for (int nn = 0; nn < 4; ++nn) {
        int cl = wn * 32 + nn * 8 + 2 * qc;
        float bq0 = quant_fixed(biasp[cout0 + cl]);
        float bq1 = quant_fixed(biasp[cout0 + cl + 1]);
        float* o0 = out_b + (size_t)(cout0 + cl) * (H * W);
        float* o1 = o0 + (H * W);
#pragma unroll
        for (int mt = 0; mt < MTS; ++mt) {
            int mA = (mt0 + mt) * 16 + qr;
            int mB = mA + 8;
            int iA = (oh_base + mA / 56) * W + (mA % 56);
            int iB = (oh_base + mB / 56) * W + (mB % 56);
            o0[iA] = acc[mt][nn][0] + bq0;
            o1[iA] = acc[mt][nn][1] + bq1;
            o0[iB] = acc[mt][nn][2] + bq0;
            o1[iB] = acc[mt][nn][3] + bq1;
        }
    }
}

__global__ __launch_bounds__(256, 2)
void conv_mma_kernel(const float* __restrict__ in,
                     const float* __restrict__ biasp,
                     float* __restrict__ out)
{
    __shared__ unsigned int s_x[1856];   // [8 ci][4 rows][58 cols] packed (hi,lo)
    __shared__ unsigned int s_w[9216];   // [9 tap][128 cout][8 pos] dup(w,w)

    const int tid = threadIdx.x;
    const int w   = tid >> 5;
    const int wm  = w & 1;
    const int wn  = w >> 1;
    const int oh_base = blockIdx.x * 2;
    const int cout0   = blockIdx.y * 128;
    const int b       = blockIdx.z;

    const float* in_b  = in  + (size_t)b * C * H * W;
    float*       out_b = out + (size_t)b * COUT * H * W;

    if (wm == 0)
        conv_body<4>(in_b, biasp, out_b, s_x, s_w, oh_base, cout0, tid, wn, 0);
    else
        conv_body<3>(in_b, biasp, out_b, s_x, s_w, oh_base, cout0, tid, wn, 4);
}

extern "C" void kernel_launch(void* const* d_in, const int* in_sizes, int n_in,
                              void* d_out, int out_size)
{
    const float* in    = (const float*)d_in[0];
    const float* shift = (const float*)d_in[1];
    const float* sign  = (const float*)d_in[2];
    const float* bias  = (const float*)d_in[3];
    float* out = (float*)d_out;

    quant_weights_kernel<<<2304, 256>>>(shift, sign);   // 256*256*9 = 2304*256
    dim3 grid(H / 2, COUT / 128, BATCH);                // 28 x 2 x 32
    conv_mma_kernel<<<grid, 256>>>(in, bias, out);
}

// round 4
// speedup vs baseline: 9.4368x; 1.7576x over previous
#include <cuda_runtime.h>
#include <cuda_fp16.h>
#include <math.h>
#include <stdint.h>

#define BATCH 32
#define C     256
#define COUT  256
#define H     56
#define W     56
#define HW    3136

// Packed quantized fp16 weights: [chunk(16)][tap(9)][cout(256)][slot(16)]
// slot order per 16-ci group: [0,1,8,9, 2,3,10,11, 4,5,12,13, 6,7,14,15]
// so thread qc's LDS.64 at byte 8*qc yields b0=(w[2qc],w[2qc+1]), b1=(w[2qc+8],w[2qc+9]).
__device__ unsigned short g_wq[16u * 9u * 256u * 16u];

__device__ __forceinline__ float quant_fixed(float x) {
    float v = floorf(x * 65536.0f) * (1.0f / 65536.0f);
    return fminf(fmaxf(v, -32768.0f), 32767.0f);
}

// ---------------- weight pre-quantization / packing ----------------
__global__ void quant_weights_kernel(const float* __restrict__ shiftp,
                                     const float* __restrict__ signp)
{
    int gid = blockIdx.x * blockDim.x + threadIdx.x;   // linear over [cout][ci][tap]
    int cout = gid / (C * 9);
    int rem  = gid - cout * (C * 9);
    int ci   = rem / 9;
    int tap  = rem - ci * 9;

    float sr = rintf(fminf(fmaxf(shiftp[gid], -14.0f), 0.0f));
    float g  = rintf(signp[gid]);
    float sg = (g > 0.0f) ? 1.0f : ((g < 0.0f) ? -1.0f : 0.0f);
    float wf = ldexpf(sg, (int)sr);                    // exact power-of-two (or 0), fp16-normal
    __half h = __float2half(wf);                       // exact

    int chunk = ci >> 4;
    int l     = ci & 15;
    int slot  = ((l >> 1) & 3) * 4 + (l >> 3) * 2 + (l & 1);
    g_wq[(((size_t)(chunk * 9 + tap) * 256 + cout) << 4) + slot] = __half_as_ushort(h);
}

// ---------------- main MMA conv ----------------
// CTA: M=112 (2 output rows), N=128 couts. 8 warps = 2(M: 4/3 mtiles) x 4(N: 32 couts).
// K-step (16) = 16 ci for one tap. 16 ci-chunks x 9 taps.

template<int MTS>
__device__ __forceinline__ void conv_body(
    const float* __restrict__ in_b,
    const float* __restrict__ biasp,
    float* __restrict__ out_b,
    uint32_t* s_x, uint32_t* s_w,
    int oh_base, int cout0, int tid, int wn, int mt0)
{
    const int lane = tid & 31;
    const int qc = lane & 3;     // k-quad
    const int qr = lane >> 2;    // m/n row within fragment

    int offA[MTS], offB[MTS];
#pragma unroll
    for (int mt = 0; mt < MTS; ++mt) {
        int mA = (mt0 + mt) * 16 + qr;
        int mB = mA + 8;
        offA[mt] = (mA / 56) * 58 + (mA % 56);
        offB[mt] = (mB / 56) * 58 + (mB % 56);
    }

    float acc[MTS][4][4];
#pragma unroll
    for (int mt = 0; mt < MTS; ++mt)
#pragma unroll
        for (int nn = 0; nn < 4; ++nn)
#pragma unroll
            for (int r = 0; r < 4; ++r) acc[mt][nn][r] = 0.0f;

    const int qc232 = qc * 232;

    for (int chunk = 0; chunk < 16; ++chunk) {
        // ---- stage x: 8 pair-planes x 4 rows x 58 cols; each word packs fp16(x[2c]),fp16(x[2c+1]) ----
        const float* inc = in_b + (size_t)chunk * 16 * HW;
#pragma unroll
        for (int it = 0; it < 8; ++it) {
            int idx = tid + it * 256;
            if (idx < 1856) {
                int c    = idx / 232;
                int rem  = idx - c * 232;
                int row  = rem / 58;
                int col  = rem - row * 58;
                int ih = oh_base + row - 1;
                int iw = col - 1;
                float v0 = 0.0f, v1 = 0.0f;
                if (ih >= 0 && ih < H && iw >= 0 && iw < W) {
                    const float* p = inc + (size_t)(2 * c) * HW + ih * W + iw;
                    v0 = quant_fixed(p[0]);
                    v1 = quant_fixed(p[HW]);
                }
                uint32_t h0 = __half_as_ushort(__float2half(v0));
                uint32_t h1 = __half_as_ushort(__float2half(v1));
                s_x[idx] = (h1 << 16) | h0;
            }
        }
        // ---- stage w: straight uint4 copy of prepacked rows ----
#pragma unroll
        for (int tap = 0; tap < 9; ++tap) {
            const uint4* src = (const uint4*)g_wq;
            ((uint4*)s_w)[tap * 256 + tid] =
                src[(size_t)(chunk * 9 + tap) * 512 + cout0 * 2 + tid];
        }
        __syncthreads();

#pragma unroll
        for (int tap = 0; tap < 9; ++tap) {
            const int kh = tap / 3, kw = tap - kh * 3;
            const int tadd = kh * 58 + kw;

            uint32_t b0[4], b1[4];
#pragma unroll
            for (int nn = 0; nn < 4; ++nn) {
                int cl = wn * 32 + nn * 8 + qr;
                uint2 bb = *(const uint2*)&s_w[tap * 1024 + cl * 8 + 2 * qc];
                b0[nn] = bb.x; b1[nn] = bb.y;
            }
#pragma unroll
            for (int mt = 0; mt < MTS; ++mt) {
                uint32_t a0 = s_x[qc232 + tadd + offA[mt]];
                uint32_t a1 = s_x[qc232 + tadd + offB[mt]];
                uint32_t a2 = s_x[qc232 + 928 + tadd + offA[mt]];
                uint32_t a3 = s_x[qc232 + 928 + tadd + offB[mt]];
#pragma unroll
                for (int nn = 0; nn < 4; ++nn) {
                    asm volatile(
                        "mma.sync.aligned.m16n8k16.row.col.f32.f16.f16.f32 "
                        "{%0,%1,%2,%3}, {%4,%5,%6,%7}, {%8,%9}, {%0,%1,%2,%3};\n"
                        : "+f"(acc[mt][nn][0]), "+f"(acc[mt][nn][1]),
                          "+f"(acc[mt][nn][2]), "+f"(acc[mt][nn][3])
                        : "r"(a0), "r"(a1), "r"(a2), "r"(a3),
                          "r"(b0[nn]), "r"(b1[nn]));
                }
            }
        }
        __syncthreads();
    }

    // ---- epilogue ----
#pragma unroll
    for (int nn = 0; nn < 4; ++nn) {
        int cl = wn * 32 + nn * 8 + 2 * qc;
        float bq0 = quant_fixed(biasp[cout0 + cl]);
        float bq1 = quant_fixed(biasp[cout0 + cl + 1]);
        float* o0 = out_b + (size_t)(cout0 + cl) * HW;
        float* o1 = o0 + HW;
#pragma unroll
        for (int mt = 0; mt < MTS; ++mt) {
            int mA = (mt0 + mt) * 16 + qr;
            int mB = mA + 8;
            int iA = (oh_base + mA / 56) * W + (mA % 56);
            int iB = (oh_base + mB / 56) * W + (mB % 56);
            o0[iA] = acc[mt][nn][0] + bq0;
            o1[iA] = acc[mt][nn][1] + bq1;
            o0[iB] = acc[mt][nn][2] + bq0;
            o1[iB] = acc[mt][nn][3] + bq1;
        }
    }
}

__global__ __launch_bounds__(256, 2)
void conv_mma_kernel(const float* __restrict__ in,
                     const float* __restrict__ biasp,
                     float* __restrict__ out)
{
    __shared__ uint32_t s_x[1856];   // 8 pair-planes x 4 rows x 58 cols (stride 232)
    __shared__ uint32_t s_w[9216];   // 9 taps x 128 couts x 8 words (32B row each)

    const int tid = threadIdx.x;
    const int w   = tid >> 5;
    const int wm  = w & 1;
    const int wn  = w >> 1;
    const int oh_base = blockIdx.x * 2;
    const int cout0   = blockIdx.y * 128;
    const int b       = blockIdx.z;

    const float* in_b  = in  + (size_t)b * C * HW;
    float*       out_b = out + (size_t)b * COUT * HW;

    if (wm == 0)
        conv_body<4>(in_b, biasp, out_b, s_x, s_w, oh_base, cout0, tid, wn, 0);
    else
        conv_body<3>(in_b, biasp, out_b, s_x, s_w, oh_base, cout0, tid, wn, 4);
}

extern "C" void kernel_launch(void* const* d_in, const int* in_sizes, int n_in,
                              void* d_out, int out_size)
{
    const float* in    = (const float*)d_in[0];
    const float* shift = (const float*)d_in[1];
    const float* sign  = (const float*)d_in[2];
    const float* bias  = (const float*)d_in[3];
    float* out = (float*)d_out;

    quant_weights_kernel<<<2304, 256>>>(shift, sign);   // 256*256*9 weights
    dim3 grid(H / 2, COUT / 128, BATCH);                // 28 x 2 x 32
    conv_mma_kernel<<<grid, 256>>>(in, bias, out);
}